// round 10
// baseline (speedup 1.0000x reference)
#include <cuda_runtime.h>
#include <cuda_fp16.h>

#define N_NODES 100000
#define N_EDGES 1600000
#define F_IN 22
#define F_HID 32
#define CAP 96                                // bucket capacity per node
#define ZERO_BLOCKS ((N_NODES + 255) / 256)   // 391
#define PLACE_BLOCKS 1184                     // 148*8
#define MAX_SPILL 4096

// ---------------- scratch (static device globals; no allocation) ----------
__device__ float g_M1[F_IN * F_HID];
__device__ float g_c1[F_HID];
__device__ float g_M2b[F_IN * F_HID];
__device__ float g_c2b[F_HID];
__device__ float g_Mp[F_IN];
__device__ float g_cp;
__device__ float g_dis[N_NODES];
__device__ int   g_slot[N_NODES];            // in-degree counter / bucket fill
__device__ int   g_is64;
__device__ int   g_spill_n;
__device__ int2  g_spill[MAX_SPILL];         // (dst, src) overflow edges
__device__ int   g_csr[(size_t)N_NODES * CAP];
__device__ __align__(16) __half g_p1h[(size_t)N_NODES * F_HID];
__device__ __align__(16) __half g_p2h[(size_t)N_NODES * F_HID];

// ---------------- prep: zero buckets + dtype sniff + weight fusion --------
__global__ void __launch_bounds__(256) k_prep(
    const void* __restrict__ ei,
    const float* __restrict__ We, const float* __restrict__ be,
    const float* __restrict__ W1, const float* __restrict__ W2,
    const float* __restrict__ Wp)
{
    int t = threadIdx.x;
    if (blockIdx.x < ZERO_BLOCKS) {
        int i = blockIdx.x * 256 + t;
        if (i < N_NODES) g_slot[i] = 0;
        if (blockIdx.x == 0) {
            const long long* p64 = (const long long*)ei;
            long long v = p64[(long long)t * (N_EDGES / 256)];
            int ok = (v >= 0 && v < N_NODES) ? 1 : 0;
            __shared__ int all_ok;
            if (t == 0) { all_ok = 1; g_spill_n = 0; }
            __syncthreads();
            if (!ok) atomicAnd(&all_ok, 0);
            __syncthreads();
            if (t == 0) g_is64 = all_ok;
        }
        return;
    }
    // weight fusion block
    for (int q = t; q < F_IN * F_HID; q += 256) {
        int k = q / F_HID, j = q % F_HID;
        float m1 = 0.f, m2b = 0.f;
        for (int u = 0; u < F_HID; ++u) {
            float we = We[k * F_HID + u];
            m1  += we * W1[u * F_HID + j];
            m2b += we * W2[(F_HID + u) * F_HID + j];
        }
        g_M1[q]  = m1;
        g_M2b[q] = m2b;
    }
    if (t < F_HID) {
        float c1 = 0.f, c2b = 0.f;
        for (int u = 0; u < F_HID; ++u) {
            c1  += be[u] * W1[u * F_HID + t];
            c2b += be[u] * W2[(F_HID + u) * F_HID + t];
        }
        g_c1[t]  = c1;
        g_c2b[t] = c2b;
    }
    if (t >= 64 && t < 64 + F_IN) {
        int k = t - 64;
        float mp = 0.f;
        for (int u = 0; u < F_HID; ++u)
            mp += We[k * F_HID + u] * Wp[F_HID + u];
        g_Mp[k] = mp;
    }
    if (t == 255) {
        float cp = 0.f;
        for (int u = 0; u < F_HID; ++u) cp += be[u] * Wp[F_HID + u];
        g_cp = cp;
    }
}

// ---------------- bucket placement (single pass over edge_index) -----------
__device__ __forceinline__ void place_edge(int s, int d)
{
    int slot = atomicAdd(&g_slot[d], 1);
    if (slot < CAP) {
        g_csr[(size_t)d * CAP + slot] = s;
    } else {
        int sp = atomicAdd(&g_spill_n, 1);
        if (sp < MAX_SPILL) g_spill[sp] = make_int2(d, s);
    }
}

__global__ void __launch_bounds__(256) k_place(const void* __restrict__ ei)
{
    int stride = gridDim.x * blockDim.x;
    if (g_is64) {
        const long long* ps = (const long long*)ei;
        const long long* pd = ps + N_EDGES;
        for (int e = blockIdx.x * blockDim.x + threadIdx.x; e < N_EDGES; e += stride)
            place_edge((int)ps[e], (int)pd[e]);
    } else {
        const int* ps = (const int*)ei;
        const int* pd = ps + N_EDGES;
        for (int e = blockIdx.x * blockDim.x + threadIdx.x; e < N_EDGES; e += stride)
            place_edge(ps[e], pd[e]);
    }
}

// ---------------- layer-1 node kernel: dis + p1 = dis*(x@M1 + c1) ----------
__global__ void __launch_bounds__(256) k_node1(const float* __restrict__ x)
{
    __shared__ float sM1[F_IN * F_HID];
    __shared__ float sc1[F_HID];
    for (int i = threadIdx.x; i < F_IN * F_HID; i += 256) sM1[i] = g_M1[i];
    if (threadIdx.x < F_HID) sc1[threadIdx.x] = g_c1[threadIdx.x];
    __syncthreads();

    int lane  = threadIdx.x & 31;
    int warp  = (blockIdx.x * 256 + threadIdx.x) >> 5;
    int nwarp = (gridDim.x * 256) >> 5;
    for (int n = warp; n < N_NODES; n += nwarp) {
        float dis = rsqrtf((float)(g_slot[n] + 1));       // +1 self loop
        if (lane == 0) g_dis[n] = dis;
        const float* xr = x + (size_t)n * F_IN;
        float acc = sc1[lane];
        #pragma unroll
        for (int k = 0; k < F_IN; ++k)
            acc += xr[k] * sM1[k * F_HID + lane];
        g_p1h[(size_t)n * F_HID + lane] = __float2half(dis * acc);
    }
}

// ---------------- helpers ----------------------------------------------------
// Load 4 fp16 message features (one 8B uint2) and widen to float4.
__device__ __forceinline__ float4 ldmsg(const __half* __restrict__ p, int s, int l)
{
    uint2 v = *reinterpret_cast<const uint2*>(p + (size_t)s * F_HID + l * 4);
    float2 f0 = __half22float2(*reinterpret_cast<const __half2*>(&v.x));
    float2 f1 = __half22float2(*reinterpret_cast<const __half2*>(&v.y));
    return make_float4(f0.x, f0.y, f1.x, f1.y);
}

// Redistribute: after xor-reduce every lane holds the float4 sum of its
// segment (lane&7). Lane j needs feature j = segment j>>2, component j&3.
__device__ __forceinline__ float redist32(float4 acc, int lane)
{
    int srcl = lane >> 2;
    float fx = __shfl_sync(0xffffffffu, acc.x, srcl);
    float fy = __shfl_sync(0xffffffffu, acc.y, srcl);
    float fz = __shfl_sync(0xffffffffu, acc.z, srcl);
    float fw = __shfl_sync(0xffffffffu, acc.w, srcl);
    int c = lane & 3;
    return (c == 0) ? fx : (c == 1) ? fy : (c == 2) ? fz : fw;
}

// Gather core: per-lane feature of a[n] = p[n] + sum_{s in in(n)} p[s].
// 4 edges in flight per 8-lane group; fp16 messages, fp32 accumulation.
__device__ __forceinline__ float gather_node(const __half* __restrict__ p, int n,
                                             int lane, int l, int g)
{
    int cnt = min(g_slot[n], CAP);
    const int* row = g_csr + (size_t)n * CAP;
    float4 acc;
    if (g == 0) {
        acc = ldmsg(p, n, l);                 // self-loop seed
    } else {
        acc = make_float4(0.f, 0.f, 0.f, 0.f);
    }
    int e = g;
    for (; e + 12 < cnt; e += 16) {
        int s0 = row[e];
        int s1 = row[e + 4];
        int s2 = row[e + 8];
        int s3 = row[e + 12];
        float4 v0 = ldmsg(p, s0, l);
        float4 v1 = ldmsg(p, s1, l);
        float4 v2 = ldmsg(p, s2, l);
        float4 v3 = ldmsg(p, s3, l);
        acc.x += (v0.x + v1.x) + (v2.x + v3.x);
        acc.y += (v0.y + v1.y) + (v2.y + v3.y);
        acc.z += (v0.z + v1.z) + (v2.z + v3.z);
        acc.w += (v0.w + v1.w) + (v2.w + v3.w);
    }
    for (; e < cnt; e += 4) {
        float4 v = ldmsg(p, row[e], l);
        acc.x += v.x; acc.y += v.y; acc.z += v.z; acc.w += v.w;
    }
    // spill edges (normally zero; single cached load when empty)
    int nsp = g_spill_n;
    if (nsp > 0) {
        if (nsp > MAX_SPILL) nsp = MAX_SPILL;
        for (int i = g; i < nsp; i += 4) {
            int2 ed = g_spill[i];
            if (ed.x == n) {
                float4 v = ldmsg(p, ed.y, l);
                acc.x += v.x; acc.y += v.y; acc.z += v.z; acc.w += v.w;
            }
        }
    }
    #pragma unroll
    for (int off = 8; off <= 16; off <<= 1) {
        acc.x += __shfl_xor_sync(0xffffffffu, acc.x, off);
        acc.y += __shfl_xor_sync(0xffffffffu, acc.y, off);
        acc.z += __shfl_xor_sync(0xffffffffu, acc.z, off);
        acc.w += __shfl_xor_sync(0xffffffffu, acc.w, off);
    }
    return redist32(acc, lane);
}

// ---------------- fused gather1 + node2 -------------------------------------
// a1 = gather(p1); r1 = relu(dis*a1 + b1); p2 = dis*(r1@W2[:32] + x@M2b + c2b)
__global__ void __launch_bounds__(256) k_gather_node2(const float* __restrict__ x,
                                                      const float* __restrict__ b1,
                                                      const float* __restrict__ W2)
{
    __shared__ float sW2t[F_HID * F_HID];
    __shared__ float sM2b[F_IN * F_HID];
    __shared__ float sc2b[F_HID];
    __shared__ float sb1[F_HID];
    for (int i = threadIdx.x; i < F_HID * F_HID; i += 256) sW2t[i] = W2[i];
    for (int i = threadIdx.x; i < F_IN * F_HID; i += 256) sM2b[i] = g_M2b[i];
    if (threadIdx.x < F_HID) { sc2b[threadIdx.x] = g_c2b[threadIdx.x];
                               sb1[threadIdx.x]  = b1[threadIdx.x]; }
    __syncthreads();

    int lane  = threadIdx.x & 31;
    int l     = lane & 7;
    int g     = lane >> 3;
    int warp  = (blockIdx.x * 256 + threadIdx.x) >> 5;
    int nwarp = (gridDim.x * 256) >> 5;

    for (int n = warp; n < N_NODES; n += nwarp) {
        float a1j = gather_node(g_p1h, n, lane, l, g);
        float dis = g_dis[n];
        float r1  = fmaxf(dis * a1j + sb1[lane], 0.f);

        const float* xr = x + (size_t)n * F_IN;
        float acc = sc2b[lane];
        #pragma unroll
        for (int k = 0; k < F_IN; ++k)
            acc += xr[k] * sM2b[k * F_HID + lane];
        #pragma unroll
        for (int k = 0; k < F_HID; ++k) {
            float rk = __shfl_sync(0xffffffffu, r1, k);
            acc += rk * sW2t[k * F_HID + lane];
        }
        g_p2h[(size_t)n * F_HID + lane] = __float2half(dis * acc);
    }
}

// ---------------- fused gather2 + prediction --------------------------------
// a2 = gather(p2); r2 = relu(dis*a2 + b2);
// out = relu(r2@Wp[:32] + x@Mp + cp + bp + x[:,1])
__global__ void __launch_bounds__(256) k_gather_final(const float* __restrict__ x,
                                                      const float* __restrict__ b2,
                                                      const float* __restrict__ Wp,
                                                      const float* __restrict__ bp,
                                                      float* __restrict__ out)
{
    __shared__ float sb2[F_HID];
    __shared__ float swp[F_HID];
    __shared__ float sMp[F_IN];
    if (threadIdx.x < F_HID) { sb2[threadIdx.x] = b2[threadIdx.x];
                               swp[threadIdx.x] = Wp[threadIdx.x]; }
    if (threadIdx.x < F_IN) sMp[threadIdx.x] = g_Mp[threadIdx.x];
    __syncthreads();

    int lane  = threadIdx.x & 31;
    int l     = lane & 7;
    int g     = lane >> 3;
    int warp  = (blockIdx.x * 256 + threadIdx.x) >> 5;
    int nwarp = (gridDim.x * 256) >> 5;
    float bias = g_cp + bp[0];

    for (int n = warp; n < N_NODES; n += nwarp) {
        float a2j = gather_node(g_p2h, n, lane, l, g);
        float dis = g_dis[n];
        float r2  = fmaxf(dis * a2j + sb2[lane], 0.f);

        const float* xr = x + (size_t)n * F_IN;
        float part = r2 * swp[lane];
        if (lane < F_IN) part += xr[lane] * sMp[lane];
        #pragma unroll
        for (int off = 16; off; off >>= 1)
            part += __shfl_xor_sync(0xffffffffu, part, off);
        if (lane == 0)
            out[n] = fmaxf(part + bias + xr[1], 0.f);
    }
}

// ---------------- launch ----------------------------------------------------
extern "C" void kernel_launch(void* const* d_in, const int* in_sizes, int n_in,
                              void* d_out, int out_size)
{
    const float* x   = (const float*)d_in[0];
    const void*  ei  = d_in[1];
    const float* We  = (const float*)d_in[2];
    const float* be  = (const float*)d_in[3];
    const float* W1  = (const float*)d_in[4];
    const float* b1  = (const float*)d_in[5];
    const float* W2  = (const float*)d_in[6];
    const float* b2  = (const float*)d_in[7];
    const float* Wp  = (const float*)d_in[8];
    const float* bp  = (const float*)d_in[9];
    float*       out = (float*)d_out;

    const int TB = 256;
    const int node1Blocks  = 2368;
    const int gatherBlocks = 2960;

    k_prep<<<ZERO_BLOCKS + 1, TB>>>(ei, We, be, W1, W2, Wp);
    k_place<<<PLACE_BLOCKS, TB>>>(ei);
    k_node1<<<node1Blocks, TB>>>(x);
    k_gather_node2<<<gatherBlocks, TB>>>(x, b1, W2);
    k_gather_final<<<gatherBlocks, TB>>>(x, b2, Wp, bp, out);
}

// round 12
// speedup vs baseline: 1.0304x; 1.0304x over previous
#include <cuda_runtime.h>
#include <cuda_fp16.h>

#define N_NODES 100000
#define N_EDGES 1600000
#define F_IN 22
#define F_HID 32
#define CAP 96                                // bucket capacity per node
#define ZERO_BLOCKS ((N_NODES + 255) / 256)   // 391
#define PLACE_BLOCKS 1184                     // 148*8
#define MAX_SPILL 4096

// ---------------- scratch (static device globals; no allocation) ----------
__device__ float g_M1[F_IN * F_HID];
__device__ float g_c1[F_HID];
__device__ float g_M2b[F_IN * F_HID];
__device__ float g_c2b[F_HID];
__device__ float g_Mp[F_IN];
__device__ float g_cp;
__device__ float g_dis[N_NODES];
__device__ int   g_slot[N_NODES];            // in-degree counter / bucket fill
__device__ int   g_is64;
__device__ int   g_spill_n;
__device__ int2  g_spill[MAX_SPILL];         // (dst, src) overflow edges
__device__ int   g_csr[(size_t)N_NODES * CAP];
__device__ __align__(16) __half g_p1h[(size_t)N_NODES * F_HID];
__device__ __align__(16) __half g_p2h[(size_t)N_NODES * F_HID];
__device__ __align__(16) __half g_q2h[(size_t)N_NODES * F_HID];  // x@M2b + c2b
__device__ float g_q3[N_NODES];                                  // x@Mp + cp + x[:,1]

// ---------------- prep: zero buckets + dtype sniff + weight fusion --------
__global__ void __launch_bounds__(256) k_prep(
    const void* __restrict__ ei,
    const float* __restrict__ We, const float* __restrict__ be,
    const float* __restrict__ W1, const float* __restrict__ W2,
    const float* __restrict__ Wp)
{
    int t = threadIdx.x;
    if (blockIdx.x < ZERO_BLOCKS) {
        int i = blockIdx.x * 256 + t;
        if (i < N_NODES) g_slot[i] = 0;
        if (blockIdx.x == 0) {
            const long long* p64 = (const long long*)ei;
            long long v = p64[(long long)t * (N_EDGES / 256)];
            int ok = (v >= 0 && v < N_NODES) ? 1 : 0;
            __shared__ int all_ok;
            if (t == 0) { all_ok = 1; g_spill_n = 0; }
            __syncthreads();
            if (!ok) atomicAnd(&all_ok, 0);
            __syncthreads();
            if (t == 0) g_is64 = all_ok;
        }
        return;
    }
    // weight fusion block
    for (int q = t; q < F_IN * F_HID; q += 256) {
        int k = q / F_HID, j = q % F_HID;
        float m1 = 0.f, m2b = 0.f;
        for (int u = 0; u < F_HID; ++u) {
            float we = We[k * F_HID + u];
            m1  += we * W1[u * F_HID + j];
            m2b += we * W2[(F_HID + u) * F_HID + j];
        }
        g_M1[q]  = m1;
        g_M2b[q] = m2b;
    }
    if (t < F_HID) {
        float c1 = 0.f, c2b = 0.f;
        for (int u = 0; u < F_HID; ++u) {
            c1  += be[u] * W1[u * F_HID + t];
            c2b += be[u] * W2[(F_HID + u) * F_HID + t];
        }
        g_c1[t]  = c1;
        g_c2b[t] = c2b;
    }
    if (t >= 64 && t < 64 + F_IN) {
        int k = t - 64;
        float mp = 0.f;
        for (int u = 0; u < F_HID; ++u)
            mp += We[k * F_HID + u] * Wp[F_HID + u];
        g_Mp[k] = mp;
    }
    if (t == 255) {
        float cp = 0.f;
        for (int u = 0; u < F_HID; ++u) cp += be[u] * Wp[F_HID + u];
        g_cp = cp;
    }
}

// ---------------- bucket placement (single pass over edge_index) -----------
__device__ __forceinline__ void place_edge(int s, int d)
{
    int slot = atomicAdd(&g_slot[d], 1);
    if (slot < CAP) {
        g_csr[(size_t)d * CAP + slot] = s;
    } else {
        int sp = atomicAdd(&g_spill_n, 1);
        if (sp < MAX_SPILL) g_spill[sp] = make_int2(d, s);
    }
}

__global__ void __launch_bounds__(256) k_place(const void* __restrict__ ei)
{
    int stride = gridDim.x * blockDim.x;
    if (g_is64) {
        const long long* ps = (const long long*)ei;
        const long long* pd = ps + N_EDGES;
        for (int e = blockIdx.x * blockDim.x + threadIdx.x; e < N_EDGES; e += stride)
            place_edge((int)ps[e], (int)pd[e]);
    } else {
        const int* ps = (const int*)ei;
        const int* pd = ps + N_EDGES;
        for (int e = blockIdx.x * blockDim.x + threadIdx.x; e < N_EDGES; e += stride)
            place_edge(ps[e], pd[e]);
    }
}

// ---------------- layer-1 node kernel ---------------------------------------
// dis; p1 = dis*(x@M1 + c1); q2 = x@M2b + c2b; q3 = x@Mp + cp + x[:,1]
__global__ void __launch_bounds__(256) k_node1(const float* __restrict__ x)
{
    __shared__ float sM1[F_IN * F_HID];
    __shared__ float sM2b[F_IN * F_HID];
    __shared__ float sc1[F_HID];
    __shared__ float sc2b[F_HID];
    __shared__ float sMp[F_IN];
    for (int i = threadIdx.x; i < F_IN * F_HID; i += 256) {
        sM1[i]  = g_M1[i];
        sM2b[i] = g_M2b[i];
    }
    if (threadIdx.x < F_HID) { sc1[threadIdx.x]  = g_c1[threadIdx.x];
                               sc2b[threadIdx.x] = g_c2b[threadIdx.x]; }
    if (threadIdx.x < F_IN) sMp[threadIdx.x] = g_Mp[threadIdx.x];
    __syncthreads();

    float cp = g_cp;
    int lane  = threadIdx.x & 31;
    int warp  = (blockIdx.x * 256 + threadIdx.x) >> 5;
    int nwarp = (gridDim.x * 256) >> 5;
    for (int n = warp; n < N_NODES; n += nwarp) {
        float dis = rsqrtf((float)(g_slot[n] + 1));       // +1 self loop
        if (lane == 0) g_dis[n] = dis;
        const float* xr = x + (size_t)n * F_IN;
        float acc1 = sc1[lane];
        float acc2 = sc2b[lane];
        float xv   = (lane < F_IN) ? xr[lane] : 0.f;      // per-lane x value
        #pragma unroll
        for (int k = 0; k < F_IN; ++k) {
            float xk = __shfl_sync(0xffffffffu, xv, k);   // broadcast from regs
            acc1 += xk * sM1[k * F_HID + lane];
            acc2 += xk * sM2b[k * F_HID + lane];
        }
        size_t o = (size_t)n * F_HID + lane;
        g_p1h[o] = __float2half(dis * acc1);
        g_q2h[o] = __float2half(acc2);
        // q3 = sum_k x_k * Mp_k  + cp + x[:,1]
        float part = (lane < F_IN) ? xv * sMp[lane] : 0.f;
        #pragma unroll
        for (int off = 16; off; off >>= 1)
            part += __shfl_xor_sync(0xffffffffu, part, off);
        float x1 = __shfl_sync(0xffffffffu, xv, 1);       // FULL warp executes
        if (lane == 0)
            g_q3[n] = part + cp + x1;
    }
}

// ---------------- helpers ----------------------------------------------------
// Load 4 fp16 message features (one 8B uint2) and widen to float4.
__device__ __forceinline__ float4 ldmsg(const __half* __restrict__ p, int s, int l)
{
    uint2 v = *reinterpret_cast<const uint2*>(p + (size_t)s * F_HID + l * 4);
    float2 f0 = __half22float2(*reinterpret_cast<const __half2*>(&v.x));
    float2 f1 = __half22float2(*reinterpret_cast<const __half2*>(&v.y));
    return make_float4(f0.x, f0.y, f1.x, f1.y);
}

// Redistribute: after xor-reduce every lane holds the float4 sum of its
// segment (lane&7). Lane j needs feature j = segment j>>2, component j&3.
__device__ __forceinline__ float redist32(float4 acc, int lane)
{
    int srcl = lane >> 2;
    float fx = __shfl_sync(0xffffffffu, acc.x, srcl);
    float fy = __shfl_sync(0xffffffffu, acc.y, srcl);
    float fz = __shfl_sync(0xffffffffu, acc.z, srcl);
    float fw = __shfl_sync(0xffffffffu, acc.w, srcl);
    int c = lane & 3;
    return (c == 0) ? fx : (c == 1) ? fy : (c == 2) ? fz : fw;
}

// Gather core: per-lane feature of a[n] = p[n] + sum_{s in in(n)} p[s].
__device__ __forceinline__ float gather_node(const __half* __restrict__ p, int n,
                                             int lane, int l, int g)
{
    int cnt = min(g_slot[n], CAP);
    const int* row = g_csr + (size_t)n * CAP;
    float4 acc;
    if (g == 0) {
        acc = ldmsg(p, n, l);                 // self-loop seed
    } else {
        acc = make_float4(0.f, 0.f, 0.f, 0.f);
    }
    int e = g;
    for (; e + 12 < cnt; e += 16) {
        int s0 = row[e];
        int s1 = row[e + 4];
        int s2 = row[e + 8];
        int s3 = row[e + 12];
        float4 v0 = ldmsg(p, s0, l);
        float4 v1 = ldmsg(p, s1, l);
        float4 v2 = ldmsg(p, s2, l);
        float4 v3 = ldmsg(p, s3, l);
        acc.x += (v0.x + v1.x) + (v2.x + v3.x);
        acc.y += (v0.y + v1.y) + (v2.y + v3.y);
        acc.z += (v0.z + v1.z) + (v2.z + v3.z);
        acc.w += (v0.w + v1.w) + (v2.w + v3.w);
    }
    for (; e < cnt; e += 4) {
        float4 v = ldmsg(p, row[e], l);
        acc.x += v.x; acc.y += v.y; acc.z += v.z; acc.w += v.w;
    }
    int nsp = g_spill_n;
    if (nsp > 0) {
        if (nsp > MAX_SPILL) nsp = MAX_SPILL;
        for (int i = g; i < nsp; i += 4) {
            int2 ed = g_spill[i];
            if (ed.x == n) {
                float4 v = ldmsg(p, ed.y, l);
                acc.x += v.x; acc.y += v.y; acc.z += v.z; acc.w += v.w;
            }
        }
    }
    #pragma unroll
    for (int off = 8; off <= 16; off <<= 1) {
        acc.x += __shfl_xor_sync(0xffffffffu, acc.x, off);
        acc.y += __shfl_xor_sync(0xffffffffu, acc.y, off);
        acc.z += __shfl_xor_sync(0xffffffffu, acc.z, off);
        acc.w += __shfl_xor_sync(0xffffffffu, acc.w, off);
    }
    return redist32(acc, lane);
}

// ---------------- fused gather1 + node2 -------------------------------------
// a1 = gather(p1); r1 = relu(dis*a1 + b1); p2 = dis*(r1@W2[:32] + q2)
__global__ void __launch_bounds__(256) k_gather_node2(const float* __restrict__ b1,
                                                      const float* __restrict__ W2)
{
    int lane  = threadIdx.x & 31;
    int l     = lane & 7;
    int g     = lane >> 3;
    int warp  = (blockIdx.x * 256 + threadIdx.x) >> 5;
    int nwarp = (gridDim.x * 256) >> 5;

    // W2 column for this lane in registers: w2c[k] = W2[k][lane]
    float w2c[F_HID];
    #pragma unroll
    for (int k = 0; k < F_HID; ++k)
        w2c[k] = W2[k * F_HID + lane];
    float b1l = b1[lane];

    for (int n = warp; n < N_NODES; n += nwarp) {
        float a1j = gather_node(g_p1h, n, lane, l, g);
        float dis = g_dis[n];
        float r1  = fmaxf(dis * a1j + b1l, 0.f);

        size_t o = (size_t)n * F_HID + lane;
        float acc = __half2float(g_q2h[o]);
        #pragma unroll
        for (int k = 0; k < F_HID; ++k) {
            float rk = __shfl_sync(0xffffffffu, r1, k);
            acc += rk * w2c[k];
        }
        g_p2h[o] = __float2half(dis * acc);
    }
}

// ---------------- fused gather2 + prediction --------------------------------
// a2 = gather(p2); r2 = relu(dis*a2 + b2); out = relu(r2@Wp[:32] + q3 + bp)
__global__ void __launch_bounds__(256) k_gather_final(const float* __restrict__ b2,
                                                      const float* __restrict__ Wp,
                                                      const float* __restrict__ bp,
                                                      float* __restrict__ out)
{
    int lane  = threadIdx.x & 31;
    int l     = lane & 7;
    int g     = lane >> 3;
    int warp  = (blockIdx.x * 256 + threadIdx.x) >> 5;
    int nwarp = (gridDim.x * 256) >> 5;
    float b2l = b2[lane];
    float wpl = Wp[lane];
    float bp0 = bp[0];

    for (int n = warp; n < N_NODES; n += nwarp) {
        float a2j = gather_node(g_p2h, n, lane, l, g);
        float dis = g_dis[n];
        float r2  = fmaxf(dis * a2j + b2l, 0.f);

        float part = r2 * wpl;
        #pragma unroll
        for (int off = 16; off; off >>= 1)
            part += __shfl_xor_sync(0xffffffffu, part, off);
        if (lane == 0)
            out[n] = fmaxf(part + g_q3[n] + bp0, 0.f);
    }
}

// ---------------- launch ----------------------------------------------------
extern "C" void kernel_launch(void* const* d_in, const int* in_sizes, int n_in,
                              void* d_out, int out_size)
{
    const float* x   = (const float*)d_in[0];
    const void*  ei  = d_in[1];
    const float* We  = (const float*)d_in[2];
    const float* be  = (const float*)d_in[3];
    const float* W1  = (const float*)d_in[4];
    const float* b1  = (const float*)d_in[5];
    const float* W2  = (const float*)d_in[6];
    const float* b2  = (const float*)d_in[7];
    const float* Wp  = (const float*)d_in[8];
    const float* bp  = (const float*)d_in[9];
    float*       out = (float*)d_out;

    const int TB = 256;
    const int node1Blocks  = 2368;
    const int gatherBlocks = 2960;

    k_prep<<<ZERO_BLOCKS + 1, TB>>>(ei, We, be, W1, W2, Wp);
    k_place<<<PLACE_BLOCKS, TB>>>(ei);
    k_node1<<<node1Blocks, TB>>>(x);
    k_gather_node2<<<gatherBlocks, TB>>>(b1, W2);
    k_gather_final<<<gatherBlocks, TB>>>(b2, Wp, bp, out);
}

// round 13
// speedup vs baseline: 1.0486x; 1.0178x over previous
#include <cuda_runtime.h>
#include <cuda_fp16.h>

#define N_NODES 100000
#define N_EDGES 1600000
#define F_IN 22
#define F_HID 32
#define CAP 96                                // bucket capacity per node
#define ZERO_BLOCKS ((N_NODES + 255) / 256)   // 391
#define PLACE_BLOCKS 1184                     // 148*8
#define MAX_SPILL 4096

// ---------------- scratch (static device globals; no allocation) ----------
__device__ float g_M1[F_IN * F_HID];
__device__ float g_c1[F_HID];
__device__ float g_M2b[F_IN * F_HID];
__device__ float g_c2b[F_HID];
__device__ float g_Mp[F_IN];
__device__ float g_cp;
__device__ float g_dis[N_NODES];
__device__ int   g_slot[N_NODES];            // in-degree counter / bucket fill
__device__ int   g_is64;
__device__ int   g_spill_n;
__device__ int2  g_spill[MAX_SPILL];         // (dst, src) overflow edges
__device__ int   g_csr[(size_t)N_NODES * CAP];
__device__ __align__(16) __half g_p1h[(size_t)N_NODES * F_HID];
__device__ __align__(16) __half g_p2h[(size_t)N_NODES * F_HID];
__device__ __align__(16) __half g_q2h[(size_t)N_NODES * F_HID];  // x@M2b + c2b
__device__ float g_q3[N_NODES];                                  // x@Mp + cp + x[:,1]

// ---------------- prep: zero buckets + dtype sniff + weight fusion --------
__global__ void __launch_bounds__(256) k_prep(
    const void* __restrict__ ei,
    const float* __restrict__ We, const float* __restrict__ be,
    const float* __restrict__ W1, const float* __restrict__ W2,
    const float* __restrict__ Wp)
{
    int t = threadIdx.x;
    if (blockIdx.x < ZERO_BLOCKS) {
        int i = blockIdx.x * 256 + t;
        if (i < N_NODES) g_slot[i] = 0;
        if (blockIdx.x == 0) {
            const long long* p64 = (const long long*)ei;
            long long v = p64[(long long)t * (N_EDGES / 256)];
            int ok = (v >= 0 && v < N_NODES) ? 1 : 0;
            __shared__ int all_ok;
            if (t == 0) { all_ok = 1; g_spill_n = 0; }
            __syncthreads();
            if (!ok) atomicAnd(&all_ok, 0);
            __syncthreads();
            if (t == 0) g_is64 = all_ok;
        }
        return;
    }
    // weight fusion block
    for (int q = t; q < F_IN * F_HID; q += 256) {
        int k = q / F_HID, j = q % F_HID;
        float m1 = 0.f, m2b = 0.f;
        for (int u = 0; u < F_HID; ++u) {
            float we = We[k * F_HID + u];
            m1  += we * W1[u * F_HID + j];
            m2b += we * W2[(F_HID + u) * F_HID + j];
        }
        g_M1[q]  = m1;
        g_M2b[q] = m2b;
    }
    if (t < F_HID) {
        float c1 = 0.f, c2b = 0.f;
        for (int u = 0; u < F_HID; ++u) {
            c1  += be[u] * W1[u * F_HID + t];
            c2b += be[u] * W2[(F_HID + u) * F_HID + t];
        }
        g_c1[t]  = c1;
        g_c2b[t] = c2b;
    }
    if (t >= 64 && t < 64 + F_IN) {
        int k = t - 64;
        float mp = 0.f;
        for (int u = 0; u < F_HID; ++u)
            mp += We[k * F_HID + u] * Wp[F_HID + u];
        g_Mp[k] = mp;
    }
    if (t == 255) {
        float cp = 0.f;
        for (int u = 0; u < F_HID; ++u) cp += be[u] * Wp[F_HID + u];
        g_cp = cp;
    }
}

// ---------------- bucket placement (single pass over edge_index) -----------
__device__ __forceinline__ void place_edge(int s, int d)
{
    int slot = atomicAdd(&g_slot[d], 1);
    if (slot < CAP) {
        g_csr[(size_t)d * CAP + slot] = s;
    } else {
        int sp = atomicAdd(&g_spill_n, 1);
        if (sp < MAX_SPILL) g_spill[sp] = make_int2(d, s);
    }
}

__global__ void __launch_bounds__(256) k_place(const void* __restrict__ ei)
{
    int stride = gridDim.x * blockDim.x;
    if (g_is64) {
        const long long* ps = (const long long*)ei;
        const long long* pd = ps + N_EDGES;
        for (int e = blockIdx.x * blockDim.x + threadIdx.x; e < N_EDGES; e += stride)
            place_edge((int)ps[e], (int)pd[e]);
    } else {
        const int* ps = (const int*)ei;
        const int* pd = ps + N_EDGES;
        for (int e = blockIdx.x * blockDim.x + threadIdx.x; e < N_EDGES; e += stride)
            place_edge(ps[e], pd[e]);
    }
}

// ---------------- layer-1 node kernel ---------------------------------------
// dis; p1 = dis*(x@M1 + c1); q2 = x@M2b + c2b; q3 = x@Mp + cp + x[:,1]
__global__ void __launch_bounds__(256) k_node1(const float* __restrict__ x)
{
    __shared__ float sM1[F_IN * F_HID];
    __shared__ float sM2b[F_IN * F_HID];
    __shared__ float sc1[F_HID];
    __shared__ float sc2b[F_HID];
    __shared__ float sMp[F_IN];
    for (int i = threadIdx.x; i < F_IN * F_HID; i += 256) {
        sM1[i]  = g_M1[i];
        sM2b[i] = g_M2b[i];
    }
    if (threadIdx.x < F_HID) { sc1[threadIdx.x]  = g_c1[threadIdx.x];
                               sc2b[threadIdx.x] = g_c2b[threadIdx.x]; }
    if (threadIdx.x < F_IN) sMp[threadIdx.x] = g_Mp[threadIdx.x];
    __syncthreads();

    float cp = g_cp;
    int lane  = threadIdx.x & 31;
    int warp  = (blockIdx.x * 256 + threadIdx.x) >> 5;
    int nwarp = (gridDim.x * 256) >> 5;
    for (int n = warp; n < N_NODES; n += nwarp) {
        float dis = rsqrtf((float)(g_slot[n] + 1));       // +1 self loop
        if (lane == 0) g_dis[n] = dis;
        const float* xr = x + (size_t)n * F_IN;
        float acc1 = sc1[lane];
        float acc2 = sc2b[lane];
        float xv   = (lane < F_IN) ? xr[lane] : 0.f;      // per-lane x value
        #pragma unroll
        for (int k = 0; k < F_IN; ++k) {
            float xk = __shfl_sync(0xffffffffu, xv, k);   // broadcast from regs
            acc1 += xk * sM1[k * F_HID + lane];
            acc2 += xk * sM2b[k * F_HID + lane];
        }
        size_t o = (size_t)n * F_HID + lane;
        g_p1h[o] = __float2half(dis * acc1);
        g_q2h[o] = __float2half(acc2);
        // q3 = sum_k x_k * Mp_k  + cp + x[:,1]
        float part = (lane < F_IN) ? xv * sMp[lane] : 0.f;
        #pragma unroll
        for (int off = 16; off; off >>= 1)
            part += __shfl_xor_sync(0xffffffffu, part, off);
        float x1 = __shfl_sync(0xffffffffu, xv, 1);       // full warp executes
        if (lane == 0)
            g_q3[n] = part + cp + x1;
    }
}

// ---------------- helpers ----------------------------------------------------
// Load 4 fp16 message features (one 8B uint2) and widen to float4.
__device__ __forceinline__ float4 ldmsg(const __half* __restrict__ p, int s, int l)
{
    uint2 v = *reinterpret_cast<const uint2*>(p + (size_t)s * F_HID + l * 4);
    float2 f0 = __half22float2(*reinterpret_cast<const __half2*>(&v.x));
    float2 f1 = __half22float2(*reinterpret_cast<const __half2*>(&v.y));
    return make_float4(f0.x, f0.y, f1.x, f1.y);
}

// Redistribute: after xor-reduce every lane holds the float4 sum of its
// segment (lane&7). Lane j needs feature j = segment j>>2, component j&3.
__device__ __forceinline__ float redist32(float4 acc, int lane)
{
    int srcl = lane >> 2;
    float fx = __shfl_sync(0xffffffffu, acc.x, srcl);
    float fy = __shfl_sync(0xffffffffu, acc.y, srcl);
    float fz = __shfl_sync(0xffffffffu, acc.z, srcl);
    float fw = __shfl_sync(0xffffffffu, acc.w, srcl);
    int c = lane & 3;
    return (c == 0) ? fx : (c == 1) ? fy : (c == 2) ? fz : fw;
}

// Gather core: per-lane feature of a[n] = p[n] + sum_{s in in(n)} p[s].
__device__ __forceinline__ float gather_node(const __half* __restrict__ p, int n,
                                             int lane, int l, int g)
{
    int cnt = min(g_slot[n], CAP);
    const int* row = g_csr + (size_t)n * CAP;
    float4 acc;
    if (g == 0) {
        acc = ldmsg(p, n, l);                 // self-loop seed
    } else {
        acc = make_float4(0.f, 0.f, 0.f, 0.f);
    }
    int e = g;
    for (; e + 12 < cnt; e += 16) {
        int s0 = row[e];
        int s1 = row[e + 4];
        int s2 = row[e + 8];
        int s3 = row[e + 12];
        float4 v0 = ldmsg(p, s0, l);
        float4 v1 = ldmsg(p, s1, l);
        float4 v2 = ldmsg(p, s2, l);
        float4 v3 = ldmsg(p, s3, l);
        acc.x += (v0.x + v1.x) + (v2.x + v3.x);
        acc.y += (v0.y + v1.y) + (v2.y + v3.y);
        acc.z += (v0.z + v1.z) + (v2.z + v3.z);
        acc.w += (v0.w + v1.w) + (v2.w + v3.w);
    }
    for (; e < cnt; e += 4) {
        float4 v = ldmsg(p, row[e], l);
        acc.x += v.x; acc.y += v.y; acc.z += v.z; acc.w += v.w;
    }
    int nsp = g_spill_n;
    if (nsp > 0) {
        if (nsp > MAX_SPILL) nsp = MAX_SPILL;
        for (int i = g; i < nsp; i += 4) {
            int2 ed = g_spill[i];
            if (ed.x == n) {
                float4 v = ldmsg(p, ed.y, l);
                acc.x += v.x; acc.y += v.y; acc.z += v.z; acc.w += v.w;
            }
        }
    }
    #pragma unroll
    for (int off = 8; off <= 16; off <<= 1) {
        acc.x += __shfl_xor_sync(0xffffffffu, acc.x, off);
        acc.y += __shfl_xor_sync(0xffffffffu, acc.y, off);
        acc.z += __shfl_xor_sync(0xffffffffu, acc.z, off);
        acc.w += __shfl_xor_sync(0xffffffffu, acc.w, off);
    }
    return redist32(acc, lane);
}

// ---------------- fused gather1 + node2 -------------------------------------
// a1 = gather(p1); r1 = relu(dis*a1 + b1); p2 = dis*(r1@W2[:32] + q2)
// W2 column read from shared (stride-32, conflict-free) to keep regs low
// and occupancy high — the register-array variant capped occ at 46%.
__global__ void __launch_bounds__(256) k_gather_node2(const float* __restrict__ b1,
                                                      const float* __restrict__ W2)
{
    __shared__ float sW2t[F_HID * F_HID];
    __shared__ float sb1[F_HID];
    for (int i = threadIdx.x; i < F_HID * F_HID; i += 256) sW2t[i] = W2[i];
    if (threadIdx.x < F_HID) sb1[threadIdx.x] = b1[threadIdx.x];
    __syncthreads();

    int lane  = threadIdx.x & 31;
    int l     = lane & 7;
    int g     = lane >> 3;
    int warp  = (blockIdx.x * 256 + threadIdx.x) >> 5;
    int nwarp = (gridDim.x * 256) >> 5;
    float b1l = sb1[lane];

    for (int n = warp; n < N_NODES; n += nwarp) {
        float a1j = gather_node(g_p1h, n, lane, l, g);
        float dis = g_dis[n];
        float r1  = fmaxf(dis * a1j + b1l, 0.f);

        size_t o = (size_t)n * F_HID + lane;
        float acc = __half2float(g_q2h[o]);
        #pragma unroll
        for (int k = 0; k < F_HID; ++k) {
            float rk = __shfl_sync(0xffffffffu, r1, k);
            acc += rk * sW2t[k * F_HID + lane];
        }
        g_p2h[o] = __float2half(dis * acc);
    }
}

// ---------------- fused gather2 + prediction --------------------------------
// a2 = gather(p2); r2 = relu(dis*a2 + b2); out = relu(r2@Wp[:32] + q3 + bp)
__global__ void __launch_bounds__(256) k_gather_final(const float* __restrict__ b2,
                                                      const float* __restrict__ Wp,
                                                      const float* __restrict__ bp,
                                                      float* __restrict__ out)
{
    int lane  = threadIdx.x & 31;
    int l     = lane & 7;
    int g     = lane >> 3;
    int warp  = (blockIdx.x * 256 + threadIdx.x) >> 5;
    int nwarp = (gridDim.x * 256) >> 5;
    float b2l = b2[lane];
    float wpl = Wp[lane];
    float bp0 = bp[0];

    for (int n = warp; n < N_NODES; n += nwarp) {
        float a2j = gather_node(g_p2h, n, lane, l, g);
        float dis = g_dis[n];
        float r2  = fmaxf(dis * a2j + b2l, 0.f);

        float part = r2 * wpl;
        #pragma unroll
        for (int off = 16; off; off >>= 1)
            part += __shfl_xor_sync(0xffffffffu, part, off);
        if (lane == 0)
            out[n] = fmaxf(part + g_q3[n] + bp0, 0.f);
    }
}

// ---------------- launch ----------------------------------------------------
extern "C" void kernel_launch(void* const* d_in, const int* in_sizes, int n_in,
                              void* d_out, int out_size)
{
    const float* x   = (const float*)d_in[0];
    const void*  ei  = d_in[1];
    const float* We  = (const float*)d_in[2];
    const float* be  = (const float*)d_in[3];
    const float* W1  = (const float*)d_in[4];
    const float* b1  = (const float*)d_in[5];
    const float* W2  = (const float*)d_in[6];
    const float* b2  = (const float*)d_in[7];
    const float* Wp  = (const float*)d_in[8];
    const float* bp  = (const float*)d_in[9];
    float*       out = (float*)d_out;

    const int TB = 256;
    const int node1Blocks  = 2368;
    const int gatherBlocks = 2960;

    k_prep<<<ZERO_BLOCKS + 1, TB>>>(ei, We, be, W1, W2, Wp);
    k_place<<<PLACE_BLOCKS, TB>>>(ei);
    k_node1<<<node1Blocks, TB>>>(x);
    k_gather_node2<<<gatherBlocks, TB>>>(b1, W2);
    k_gather_final<<<gatherBlocks, TB>>>(b2, Wp, bp, out);
}